// round 1
// baseline (speedup 1.0000x reference)
#include <cuda_runtime.h>

// ---------------------------------------------------------------------------
// LSTM_6786048328562 : T=512, B=32, I=H=1024
//   out = [ output(512*32*1024) | h_n(32*1024) | c_n(32*1024) ]  (fp32)
//
// Plan:
//   prep_kernel : reorder W,U rows to gate-group layout (j' = 128*(n/32) +
//                 gate*32 + n%32), round to tf32, combine biases, zero h
//                 buffers, reset barrier counters (stream-ordered => safe).
//   gemm_xg     : xg[t*B+b][j'] = sum_k x[t,b,k]*W'[j'][k] + bias'[j']
//                 (tf32 mma.sync, 128x128x32 tiles)
//   lstm_kernel : persistent, 128 CTAs (32 gate-groups x 4 K-splits).
//                 U' slice lives in SMEM for the whole kernel. Per step:
//                 load h slice -> mma partial -> group sync -> leader reduces
//                 4 partials + xg, applies gates, updates c (SMEM), writes
//                 output row + tf32-rounded h -> global barrier.
// ---------------------------------------------------------------------------

#define T_STEPS 512
#define BATCH   32
#define HID     1024
#define GATES   4096
#define ROWS_TB 16384          // T*B
#define NSPLIT  4
#define KSLICE  256            // HID / NSPLIT

// ---- scratch (device globals; no allocations allowed) ----
__device__ float d_xg[67108864];              // [16384][4096]  268 MB
__device__ float d_Wp[GATES * HID];           // reordered, tf32-rounded
__device__ float d_Up[GATES * HID];
__device__ float d_biasp[GATES];
__device__ float d_hbuf[2 * BATCH * HID];     // double-buffered h (tf32-rounded)
__device__ float d_part[NSPLIT * GATES * BATCH]; // split-K partials [s][j'][b]
__device__ unsigned g_bar;
__device__ unsigned g_grp[32];

// ---- helpers ----
__device__ __forceinline__ float f2tf32(float f) {
    unsigned u;
    asm("cvt.rna.tf32.f32 %0, %1;" : "=r"(u) : "f"(f));
    return __uint_as_float(u);
}

__device__ __forceinline__ void mma_tf32(float* c, const unsigned* a, const unsigned* b) {
    asm volatile(
        "mma.sync.aligned.m16n8k8.row.col.f32.tf32.tf32.f32 "
        "{%0,%1,%2,%3}, {%4,%5,%6,%7}, {%8,%9}, {%0,%1,%2,%3};\n"
        : "+f"(c[0]), "+f"(c[1]), "+f"(c[2]), "+f"(c[3])
        : "r"(a[0]), "r"(a[1]), "r"(a[2]), "r"(a[3]), "r"(b[0]), "r"(b[1]));
}

__device__ __forceinline__ float sigm(float x) { return 1.0f / (1.0f + expf(-x)); }

// ---------------------------------------------------------------------------
// prep: reorder + round weights, biases; zero h buffers; reset barriers.
// Row map: j' = 128*g + gate*32 + nl  with  n = 32*g + nl,  j = gate*1024 + n
// ---------------------------------------------------------------------------
__global__ void prep_kernel(const float* __restrict__ W, const float* __restrict__ U,
                            const float* __restrict__ bih, const float* __restrict__ bhh) {
    int tid = blockIdx.x * blockDim.x + threadIdx.x;
    int stride = gridDim.x * blockDim.x;
    if (tid == 0) g_bar = 0u;
    if (tid < 32) g_grp[tid] = 0u;

    for (int idx = tid; idx < GATES * HID; idx += stride) {
        int jp = idx >> 10;
        int k  = idx & 1023;
        int g = jp >> 7, r = jp & 127;
        int gate = r >> 5, nl = r & 31;
        int j = gate * HID + (g * 32 + nl);
        d_Wp[idx] = f2tf32(W[j * HID + k]);
        d_Up[idx] = f2tf32(U[j * HID + k]);
    }
    for (int idx = tid; idx < GATES; idx += stride) {
        int g = idx >> 7, r = idx & 127;
        int gate = r >> 5, nl = r & 31;
        int j = gate * HID + (g * 32 + nl);
        d_biasp[idx] = bih[j] + bhh[j];
    }
    for (int idx = tid; idx < 2 * BATCH * HID; idx += stride) d_hbuf[idx] = 0.0f;
}

// ---------------------------------------------------------------------------
// Phase 1: xg = x @ W'^T + bias'   (M=16384, N=4096, K=1024)
// 128x128 CTA tile, BK=32, 8 warps (2m x 4n), warp tile 64x32, tf32 mma.
// ---------------------------------------------------------------------------
#define P1_AS 36   // smem row stride (bank-conflict-free, float4-aligned)

__global__ __launch_bounds__(256) void gemm_xg(const float* __restrict__ x) {
    __shared__ float As[128 * P1_AS];
    __shared__ float Bs[128 * P1_AS];

    const int n0 = blockIdx.x * 128;
    const int m0 = blockIdx.y * 128;
    const int tid = threadIdx.x;
    const int warp = tid >> 5, lane = tid & 31;
    const int wm = warp >> 2, wn = warp & 3;
    const int gid = lane >> 2, tg = lane & 3;

    float acc[4][4][4];
#pragma unroll
    for (int i = 0; i < 4; i++)
#pragma unroll
        for (int j = 0; j < 4; j++)
#pragma unroll
            for (int k = 0; k < 4; k++) acc[i][j][k] = 0.0f;

    const float* Ag = x + (size_t)m0 * HID;
    const float* Bg = d_Wp + (size_t)n0 * HID;
    const int lr = tid >> 3;        // 0..31
    const int lc = (tid & 7) * 4;   // 0..28

    for (int kt = 0; kt < 32; kt++) {
        const int k0 = kt * 32;
#pragma unroll
        for (int r = 0; r < 4; r++) {
            int row = lr + r * 32;
            float4 av = *(const float4*)(Ag + row * HID + k0 + lc);
            av.x = f2tf32(av.x); av.y = f2tf32(av.y);
            av.z = f2tf32(av.z); av.w = f2tf32(av.w);
            *(float4*)(As + row * P1_AS + lc) = av;
            float4 bv = *(const float4*)(Bg + row * HID + k0 + lc); // pre-rounded
            *(float4*)(Bs + row * P1_AS + lc) = bv;
        }
        __syncthreads();

#pragma unroll
        for (int kk = 0; kk < 4; kk++) {
            const int kc = kk * 8 + tg;
            unsigned a[4][4], b[4][2];
#pragma unroll
            for (int mf = 0; mf < 4; mf++) {
                int row = wm * 64 + mf * 16 + gid;
                a[mf][0] = __float_as_uint(As[row * P1_AS + kc]);
                a[mf][1] = __float_as_uint(As[(row + 8) * P1_AS + kc]);
                a[mf][2] = __float_as_uint(As[row * P1_AS + kc + 4]);
                a[mf][3] = __float_as_uint(As[(row + 8) * P1_AS + kc + 4]);
            }
#pragma unroll
            for (int nf = 0; nf < 4; nf++) {
                int col = wn * 32 + nf * 8 + gid;
                b[nf][0] = __float_as_uint(Bs[col * P1_AS + kc]);
                b[nf][1] = __float_as_uint(Bs[col * P1_AS + kc + 4]);
            }
#pragma unroll
            for (int mf = 0; mf < 4; mf++)
#pragma unroll
                for (int nf = 0; nf < 4; nf++) mma_tf32(acc[mf][nf], a[mf], b[nf]);
        }
        __syncthreads();
    }

#pragma unroll
    for (int mf = 0; mf < 4; mf++) {
#pragma unroll
        for (int nf = 0; nf < 4; nf++) {
            int row = m0 + wm * 64 + mf * 16 + gid;
            int col = n0 + wn * 32 + nf * 8 + 2 * tg;
            float b0 = d_biasp[col], b1 = d_biasp[col + 1];
            d_xg[row * GATES + col]           = acc[mf][nf][0] + b0;
            d_xg[row * GATES + col + 1]       = acc[mf][nf][1] + b1;
            d_xg[(row + 8) * GATES + col]     = acc[mf][nf][2] + b0;
            d_xg[(row + 8) * GATES + col + 1] = acc[mf][nf][3] + b1;
        }
    }
}

// ---------------------------------------------------------------------------
// Phase 2: persistent recurrent kernel. 128 CTAs = 32 groups x 4 K-splits.
// CTA (g,s): D[128 j' rows of group g][32 b] over k in [256s, 256s+256).
// Leader (s==0) reduces the 4 partials + xg, does gate math, owns c in SMEM.
// ---------------------------------------------------------------------------
#define P2_US 260  // smem row stride (260 % 32 == 4 -> conflict-free; /4 aligned)

__global__ __launch_bounds__(256, 1) void lstm_kernel(float* __restrict__ out) {
    extern __shared__ float sm[];
    float* Us = sm;                       // 128 x 260
    float* hs = sm + 128 * P2_US;         // 32 x 260
    float* cs = sm + 128 * P2_US + 32 * P2_US; // 1024 (leader's c state)

    const int cta = blockIdx.x;
    const int g = cta >> 2, s = cta & 3;
    const int tid = threadIdx.x;
    const int warp = tid >> 5, lane = tid & 31;
    const int gid = lane >> 2, tg = lane & 3;
    const int row0 = 16 * warp + gid;     // warp's A row within 128-row tile

    // Stage U' slice [128 rows of group g][256 k of split s] into SMEM (once).
    const float* Ug = d_Up + (128 * g) * HID + KSLICE * s;
    for (int i = tid; i < 128 * 64; i += 256) {
        int row = i >> 6, c4 = (i & 63) * 4;
        *(float4*)(Us + row * P2_US + c4) = *(const float4*)(Ug + row * HID + c4);
    }
    if (s == 0)
        for (int i = tid; i < 1024; i += 256) cs[i] = 0.0f;
    __syncthreads();

    for (int t = 0; t < T_STEPS; t++) {
        // load h slice [32][256] (written by other SMs -> bypass L1)
        const float* hsrc = d_hbuf + (t & 1) * (BATCH * HID) + KSLICE * s;
        for (int i = tid; i < 32 * 64; i += 256) {
            int b = i >> 6, c4 = (i & 63) * 4;
            float4 v;
            v.x = __ldcg(hsrc + b * HID + c4);
            v.y = __ldcg(hsrc + b * HID + c4 + 1);
            v.z = __ldcg(hsrc + b * HID + c4 + 2);
            v.w = __ldcg(hsrc + b * HID + c4 + 3);
            *(float4*)(hs + b * P2_US + c4) = v;
        }
        __syncthreads();

        float acc[4][4];
#pragma unroll
        for (int i = 0; i < 4; i++)
#pragma unroll
            for (int j = 0; j < 4; j++) acc[i][j] = 0.0f;

#pragma unroll
        for (int kk = 0; kk < 32; kk++) {
            const int kc = kk * 8 + tg;
            unsigned a[4];
            a[0] = __float_as_uint(Us[row0 * P2_US + kc]);
            a[1] = __float_as_uint(Us[(row0 + 8) * P2_US + kc]);
            a[2] = __float_as_uint(Us[row0 * P2_US + kc + 4]);
            a[3] = __float_as_uint(Us[(row0 + 8) * P2_US + kc + 4]);
#pragma unroll
            for (int nf = 0; nf < 4; nf++) {
                unsigned b[2];
                b[0] = __float_as_uint(hs[(nf * 8 + gid) * P2_US + kc]);
                b[1] = __float_as_uint(hs[(nf * 8 + gid) * P2_US + kc + 4]);
                mma_tf32(acc[nf], a, b);
            }
        }

        // write split-K partial: d_part[s][128g + row][b]
        float* pp = d_part + s * (GATES * BATCH) + (128 * g) * BATCH;
#pragma unroll
        for (int nf = 0; nf < 4; nf++) {
            int b = nf * 8 + 2 * tg;
            pp[row0 * BATCH + b]           = acc[nf][0];
            pp[row0 * BATCH + b + 1]       = acc[nf][1];
            pp[(row0 + 8) * BATCH + b]     = acc[nf][2];
            pp[(row0 + 8) * BATCH + b + 1] = acc[nf][3];
        }
        __threadfence();
        __syncthreads();
        if (tid == 0) atomicAdd(&g_grp[g], 1u);

        if (s == 0) {
            if (tid == 0) {
                volatile unsigned* p = &g_grp[g];
                while (*p < 4u * (unsigned)(t + 1)) { __nanosleep(40); }
            }
            __threadfence();
            __syncthreads();

            // reduce 4 partials + xg, gate math, c update, emit h
            const float* xgrow = d_xg + (size_t)(t * BATCH) * GATES + 128 * g;
            const float* p0 = d_part + (128 * g) * BATCH;
            for (int idx = tid; idx < 1024; idx += 256) {
                int b = idx >> 5, nl = idx & 31;
                float v[4];
#pragma unroll
                for (int gate = 0; gate < 4; gate++) {
                    int r = gate * 32 + nl;
                    float sum = xgrow[b * GATES + r];
                    sum += __ldcg(p0 + r * BATCH + b);
                    sum += __ldcg(p0 + GATES * BATCH + r * BATCH + b);
                    sum += __ldcg(p0 + 2 * GATES * BATCH + r * BATCH + b);
                    sum += __ldcg(p0 + 3 * GATES * BATCH + r * BATCH + b);
                    v[gate] = sum;
                }
                float it = sigm(v[0]);
                float ft = sigm(v[1]);
                float ch = tanhf(v[2]);
                float ot = sigm(v[3]);
                float c = ft * cs[idx] + it * ch;
                cs[idx] = c;
                float h = ot * tanhf(c);
                int n = g * 32 + nl;
                out[(size_t)t * (BATCH * HID) + b * HID + n] = h;
                d_hbuf[((t + 1) & 1) * (BATCH * HID) + b * HID + n] = f2tf32(h);
                if (t == T_STEPS - 1) {
                    out[16777216 + b * HID + n] = h;           // h_n
                    out[16777216 + 32768 + b * HID + n] = c;   // c_n
                }
            }
            __threadfence();
            __syncthreads();
        }

        // global barrier (monotonic counter, reset by next launch's prep)
        if (tid == 0) {
            atomicAdd(&g_bar, 1u);
            volatile unsigned* pb = &g_bar;
            while (*pb < 128u * (unsigned)(t + 1)) { __nanosleep(40); }
        }
        __threadfence();
        __syncthreads();
    }
}

// ---------------------------------------------------------------------------
extern "C" void kernel_launch(void* const* d_in, const int* in_sizes, int n_in,
                              void* d_out, int out_size) {
    (void)in_sizes; (void)n_in; (void)out_size;
    const float* x   = (const float*)d_in[0];
    const float* W   = (const float*)d_in[1];
    const float* U   = (const float*)d_in[2];
    const float* bih = (const float*)d_in[3];
    const float* bhh = (const float*)d_in[4];
    float* out = (float*)d_out;

    const int smem2 = (128 * P2_US + 32 * P2_US + 1024) * 4; // 170,496 B
    cudaFuncSetAttribute(lstm_kernel, cudaFuncAttributeMaxDynamicSharedMemorySize, smem2);

    prep_kernel<<<4096, 256>>>(W, U, bih, bhh);
    dim3 g1(32, 128);
    gemm_xg<<<g1, 256>>>(x);
    lstm_kernel<<<128, 256, smem2>>>(out);
}

// round 2
// speedup vs baseline: 3.5971x; 3.5971x over previous
#include <cuda_runtime.h>

// ---------------------------------------------------------------------------
// LSTM_6786048328562 : T=512, B=32, I=H=1024  (fp32 in/out, tf32 tensor math)
//   out = [ output(512*32*1024) | h_n(32*1024) | c_n(32*1024) ]
//
// Row reorder:  j'' = 32*blk + gate*8 + u   (hidden n = 8*blk + u, blk=0..127)
//   -> CTA blk of the recurrent kernel owns ALL 4 gates of hidden 8*blk..+7.
//
// prep    : reorder+tf32-round W,U; tf32-round x -> d_xr; bias; zero h; bar=0
// gemm_xg : xg = xr @ W''^T + bias  (tf32 mma, 128x128x32, 2-stage cp.async)
// lstm    : persistent 128 CTAs. U'' slice (32x1024) SMEM-resident. Per step:
//           stream h in 4 chunks (cp.async.cg double buffer) overlapped with
//           K-split-across-warps MMA; deterministic smem reduce; local gate
//           math (c in registers); ONE global barrier per step.
// ---------------------------------------------------------------------------

#define T_STEPS 512
#define BATCH   32
#define HID     1024
#define GATES   4096

__device__ float d_xg[67108864];          // [16384][4096]
__device__ float d_xr[16777216];          // tf32-rounded x
__device__ float d_Wp[GATES * HID];
__device__ float d_Up[GATES * HID];
__device__ float d_biasp[GATES];
__device__ float d_hbuf[2 * BATCH * HID]; // double-buffered h (tf32-rounded)
__device__ unsigned g_bar;

__device__ __forceinline__ float f2tf32(float f) {
    unsigned u;
    asm("cvt.rna.tf32.f32 %0, %1;" : "=r"(u) : "f"(f));
    return __uint_as_float(u);
}

__device__ __forceinline__ void mma_tf32(float* c, const unsigned* a, const unsigned* b) {
    asm volatile(
        "mma.sync.aligned.m16n8k8.row.col.f32.tf32.tf32.f32 "
        "{%0,%1,%2,%3}, {%4,%5,%6,%7}, {%8,%9}, {%0,%1,%2,%3};\n"
        : "+f"(c[0]), "+f"(c[1]), "+f"(c[2]), "+f"(c[3])
        : "r"(a[0]), "r"(a[1]), "r"(a[2]), "r"(a[3]), "r"(b[0]), "r"(b[1]));
}

__device__ __forceinline__ float sigm(float x) { return 1.0f / (1.0f + expf(-x)); }

#define CP_ASYNC_CG(dst, src) \
    asm volatile("cp.async.cg.shared.global [%0], [%1], 16;\n" :: "r"(dst), "l"(src))
#define CP_COMMIT() asm volatile("cp.async.commit_group;\n")
#define CP_WAIT(n)  asm volatile("cp.async.wait_group %0;\n" :: "n"(n))

// ---------------------------------------------------------------------------
__global__ void prep_kernel(const float* __restrict__ x,
                            const float* __restrict__ W, const float* __restrict__ U,
                            const float* __restrict__ bih, const float* __restrict__ bhh) {
    int tid = blockIdx.x * blockDim.x + threadIdx.x;
    int stride = gridDim.x * blockDim.x;
    if (tid == 0) g_bar = 0u;

    for (int idx = tid; idx < GATES * HID; idx += stride) {
        int jp = idx >> 10, k = idx & 1023;
        int blk = jp >> 5, r = jp & 31;
        int gate = r >> 3, u = r & 7;
        int j = gate * HID + (blk * 8 + u);
        d_Wp[idx] = f2tf32(W[j * HID + k]);
        d_Up[idx] = f2tf32(U[j * HID + k]);
    }
    for (int idx = tid; idx < 16777216; idx += stride) d_xr[idx] = f2tf32(x[idx]);
    for (int idx = tid; idx < GATES; idx += stride) {
        int blk = idx >> 5, r = idx & 31;
        int gate = r >> 3, u = r & 7;
        int j = gate * HID + (blk * 8 + u);
        d_biasp[idx] = bih[j] + bhh[j];
    }
    for (int idx = tid; idx < 2 * BATCH * HID; idx += stride) d_hbuf[idx] = 0.0f;
}

// ---------------------------------------------------------------------------
// Phase 1: xg = xr @ Wp^T + bias   (M=16384, N=4096, K=1024)
// ---------------------------------------------------------------------------
#define P1_S 36

__global__ __launch_bounds__(256) void gemm_xg() {
    extern __shared__ float sm1[];
    float* As = sm1;                  // [2][128*36]
    float* Bs = sm1 + 2 * 128 * P1_S; // [2][128*36]

    const int n0 = blockIdx.x * 128;
    const int m0 = blockIdx.y * 128;
    const int tid = threadIdx.x;
    const int warp = tid >> 5, lane = tid & 31;
    const int wm = warp >> 2, wn = warp & 3;
    const int gid = lane >> 2, tg = lane & 3;

    float acc[4][4][4];
#pragma unroll
    for (int i = 0; i < 4; i++)
#pragma unroll
        for (int j = 0; j < 4; j++)
#pragma unroll
            for (int k = 0; k < 4; k++) acc[i][j][k] = 0.0f;

    const float* Ag = d_xr + (size_t)m0 * HID;
    const float* Bg = d_Wp + (size_t)n0 * HID;

    auto load_stage = [&](int kt, int st) {
        float* Ad = As + st * 128 * P1_S;
        float* Bd = Bs + st * 128 * P1_S;
        const int k0 = kt * 32;
#pragma unroll
        for (int l = 0; l < 4; l++) {
            int i = tid + l * 256;           // 0..1023
            int row = i >> 3, v = (i & 7) * 4;
            unsigned da = (unsigned)__cvta_generic_to_shared(Ad + row * P1_S + v);
            CP_ASYNC_CG(da, Ag + (size_t)row * HID + k0 + v);
            unsigned db = (unsigned)__cvta_generic_to_shared(Bd + row * P1_S + v);
            CP_ASYNC_CG(db, Bg + (size_t)row * HID + k0 + v);
        }
        CP_COMMIT();
    };

    load_stage(0, 0);
    for (int kt = 0; kt < 32; kt++) {
        if (kt + 1 < 32) { load_stage(kt + 1, (kt + 1) & 1); CP_WAIT(1); }
        else             { CP_WAIT(0); }
        __syncthreads();
        const float* Ac = As + (kt & 1) * 128 * P1_S;
        const float* Bc = Bs + (kt & 1) * 128 * P1_S;
#pragma unroll
        for (int kk = 0; kk < 4; kk++) {
            const int kc = kk * 8 + tg;
            unsigned a[4][4], b[4][2];
#pragma unroll
            for (int mf = 0; mf < 4; mf++) {
                int row = wm * 64 + mf * 16 + gid;
                a[mf][0] = __float_as_uint(Ac[row * P1_S + kc]);
                a[mf][1] = __float_as_uint(Ac[(row + 8) * P1_S + kc]);
                a[mf][2] = __float_as_uint(Ac[row * P1_S + kc + 4]);
                a[mf][3] = __float_as_uint(Ac[(row + 8) * P1_S + kc + 4]);
            }
#pragma unroll
            for (int nf = 0; nf < 4; nf++) {
                int col = wn * 32 + nf * 8 + gid;
                b[nf][0] = __float_as_uint(Bc[col * P1_S + kc]);
                b[nf][1] = __float_as_uint(Bc[col * P1_S + kc + 4]);
            }
#pragma unroll
            for (int mf = 0; mf < 4; mf++)
#pragma unroll
                for (int nf = 0; nf < 4; nf++) mma_tf32(acc[mf][nf], a[mf], b[nf]);
        }
        __syncthreads();
    }

#pragma unroll
    for (int mf = 0; mf < 4; mf++)
#pragma unroll
        for (int nf = 0; nf < 4; nf++) {
            int row = m0 + wm * 64 + mf * 16 + gid;
            int col = n0 + wn * 32 + nf * 8 + 2 * tg;
            float b0 = d_biasp[col], b1 = d_biasp[col + 1];
            d_xg[(size_t)row * GATES + col]           = acc[mf][nf][0] + b0;
            d_xg[(size_t)row * GATES + col + 1]       = acc[mf][nf][1] + b1;
            d_xg[(size_t)(row + 8) * GATES + col]     = acc[mf][nf][2] + b0;
            d_xg[(size_t)(row + 8) * GATES + col + 1] = acc[mf][nf][3] + b1;
        }
}

// ---------------------------------------------------------------------------
// Phase 2: persistent recurrence. 128 CTAs, CTA owns 32 gate-rows, full K.
// ---------------------------------------------------------------------------
#define SU 1028                 // Us row stride (floats)
#define SH 260                  // h chunk row stride
#define RBS (32 * 33)           // per-warp reduce buffer
#define OFF_HS (32 * SU)        // 32896
#define OFF_RB (OFF_HS + 2 * 32 * SH)

__global__ __launch_bounds__(256, 1) void lstm_kernel(float* __restrict__ out) {
    extern __shared__ float sm[];
    float* Us = sm;                  // 32 x 1028
    float* hs = sm + OFF_HS;         // 2 x 32 x 260
    float* rb = sm + OFF_RB;         // 8 x 32 x 33

    const int cta = blockIdx.x;
    const int tid = threadIdx.x;
    const int warp = tid >> 5, lane = tid & 31;
    const int gid = lane >> 2, tg = lane & 3;

    // stage U'' slice (rows 32*cta .. +31, all K) once
    const float* Ug = d_Up + (size_t)(32 * cta) * HID;
    for (int i = tid; i < 32 * 256; i += 256) {
        int row = i >> 8, v = (i & 255) * 4;
        *(float4*)(Us + row * SU + v) = *(const float4*)(Ug + row * HID + v);
    }
    __syncthreads();

    // thread-owned cell state: thread (u = tid>>5, b = tid&31) owns c[u][b]
    const int tu = tid >> 5, tb = tid & 31;
    float c_reg = 0.0f;

    float* outp = out;

    for (int t = 0; t < T_STEPS; t++) {
        const float* hb = d_hbuf + (t & 1) * (BATCH * HID);

        auto load_chunk = [&](int ch, int bi) {
#pragma unroll
            for (int l = 0; l < 8; l++) {
                int i = tid + l * 256;          // 0..2047
                int row = i >> 6, v = (i & 63) * 4;
                unsigned d = (unsigned)__cvta_generic_to_shared(
                    hs + bi * (32 * SH) + row * SH + v);
                CP_ASYNC_CG(d, hb + row * HID + ch * 256 + v);
            }
            CP_COMMIT();
        };

        float acc[2][4][4];
#pragma unroll
        for (int i = 0; i < 2; i++)
#pragma unroll
            for (int j = 0; j < 4; j++)
#pragma unroll
                for (int k = 0; k < 4; k++) acc[i][j][k] = 0.0f;

        auto mma_chunk = [&](int ch, int bi) {
            const float* hc = hs + bi * (32 * SH);
            const int kb = warp * 32;
#pragma unroll
            for (int kk = 0; kk < 4; kk++) {
                const int kcl = kb + kk * 8 + tg;       // 0..255 within chunk
                const int kcu = ch * 256 + kcl;         // 0..1023 in Us
                unsigned a[2][4];
#pragma unroll
                for (int mt = 0; mt < 2; mt++) {
                    int row = mt * 16 + gid;
                    a[mt][0] = __float_as_uint(Us[row * SU + kcu]);
                    a[mt][1] = __float_as_uint(Us[(row + 8) * SU + kcu]);
                    a[mt][2] = __float_as_uint(Us[row * SU + kcu + 4]);
                    a[mt][3] = __float_as_uint(Us[(row + 8) * SU + kcu + 4]);
                }
#pragma unroll
                for (int nf = 0; nf < 4; nf++) {
                    unsigned b[2];
                    b[0] = __float_as_uint(hc[(nf * 8 + gid) * SH + kcl]);
                    b[1] = __float_as_uint(hc[(nf * 8 + gid) * SH + kcl + 4]);
#pragma unroll
                    for (int mt = 0; mt < 2; mt++) mma_tf32(acc[mt][nf], a[mt], b);
                }
            }
        };

        load_chunk(0, 0);
        load_chunk(1, 1);
        CP_WAIT(1); __syncthreads();
        mma_chunk(0, 0);
        __syncthreads();
        load_chunk(2, 0);
        CP_WAIT(1); __syncthreads();
        mma_chunk(1, 1);
        __syncthreads();
        load_chunk(3, 1);
        CP_WAIT(1); __syncthreads();
        mma_chunk(2, 0);
        CP_WAIT(0); __syncthreads();
        mma_chunk(3, 1);

        // deterministic cross-warp reduce: every warp dumps its partial
        float* rbw = rb + warp * RBS;
#pragma unroll
        for (int mt = 0; mt < 2; mt++)
#pragma unroll
            for (int nf = 0; nf < 4; nf++) {
                int row = mt * 16 + gid;
                int col = nf * 8 + 2 * tg;
                rbw[row * 33 + col]           = acc[mt][nf][0];
                rbw[row * 33 + col + 1]       = acc[mt][nf][1];
                rbw[(row + 8) * 33 + col]     = acc[mt][nf][2];
                rbw[(row + 8) * 33 + col + 1] = acc[mt][nf][3];
            }
        __syncthreads();

        // gate math: thread (tu, tb)
        {
            const float* xgr = d_xg + (size_t)(t * BATCH + tb) * GATES + 32 * cta;
            float v[4];
#pragma unroll
            for (int gate = 0; gate < 4; gate++) {
                int r = gate * 8 + tu;
                float s = __ldg(xgr + r);
#pragma unroll
                for (int p = 0; p < 8; p++) s += rb[p * RBS + r * 33 + tb];
                v[gate] = s;
            }
            float it = sigm(v[0]);
            float ft = sigm(v[1]);
            float ch = tanhf(v[2]);
            float ot = sigm(v[3]);
            c_reg = ft * c_reg + it * ch;
            float h = ot * tanhf(c_reg);
            int n = 8 * cta + tu;
            outp[(size_t)t * (BATCH * HID) + tb * HID + n] = h;
            d_hbuf[((t + 1) & 1) * (BATCH * HID) + tb * HID + n] = f2tf32(h);
            if (t == T_STEPS - 1) {
                outp[16777216 + tb * HID + n] = h;
                outp[16777216 + 32768 + tb * HID + n] = c_reg;
            }
        }

        // single global barrier
        __threadfence();
        __syncthreads();
        if (tid == 0) {
            atomicAdd(&g_bar, 1u);
            volatile unsigned* pb = &g_bar;
            while (*pb < 128u * (unsigned)(t + 1)) { }
        }
        __syncthreads();
    }
}

// ---------------------------------------------------------------------------
extern "C" void kernel_launch(void* const* d_in, const int* in_sizes, int n_in,
                              void* d_out, int out_size) {
    (void)in_sizes; (void)n_in; (void)out_size;
    const float* x   = (const float*)d_in[0];
    const float* W   = (const float*)d_in[1];
    const float* U   = (const float*)d_in[2];
    const float* bih = (const float*)d_in[3];
    const float* bhh = (const float*)d_in[4];
    float* out = (float*)d_out;

    static int inited = 0;
    const int smem1 = 2 * 2 * 128 * P1_S * 4;                     // 73,728
    const int smem2 = (OFF_RB + 8 * RBS) * 4;                     // 231,936
    if (!inited) {
        cudaFuncSetAttribute(gemm_xg, cudaFuncAttributeMaxDynamicSharedMemorySize, smem1);
        cudaFuncSetAttribute(lstm_kernel, cudaFuncAttributeMaxDynamicSharedMemorySize, smem2);
        inited = 1;
    }

    prep_kernel<<<4096, 256>>>(x, W, U, bih, bhh);
    dim3 g1(32, 128);
    gemm_xg<<<g1, 256, smem1>>>();
    lstm_kernel<<<128, 256, smem2>>>(out);
}

// round 3
// speedup vs baseline: 3.8878x; 1.0808x over previous
#include <cuda_runtime.h>

// ---------------------------------------------------------------------------
// LSTM_6786048328562 : T=512, B=32, I=H=1024  (fp32 in/out, tf32 tensor math)
//   out = [ output(512*32*1024) | h_n(32*1024) | c_n(32*1024) ]
//
// Row reorder:  j'' = 32*blk + gate*8 + u   (hidden n = 8*blk + u, blk=0..127)
//   -> CTA blk of the recurrent kernel owns ALL 4 gates of hidden 8*blk..+7.
//
// prep    : reorder+tf32-round W,U; tf32-round x; bias; zero h; bar=0
// gemm_xg : xg = xr @ W''^T + bias  (tf32 mma, 128x128x32, 2-stage cp.async)
// lstm    : persistent 128 CTAs. U'' (32x1024) SMEM-resident. Per step:
//           prefetch xg tile (cp.async, off critical path), stream h in 4
//           double-buffered cp.async chunks overlapped with K-split MMA,
//           two-phase smem reduce, local gate math (c in regs), ONE
//           release/acquire global barrier (red.release + ld.acquire spin).
// ---------------------------------------------------------------------------

#define T_STEPS 512
#define BATCH   32
#define HID     1024
#define GATES   4096

__device__ float d_xg[67108864];          // [16384][4096]
__device__ float d_xr[16777216];          // tf32-rounded x
__device__ float d_Wp[GATES * HID];
__device__ float d_Up[GATES * HID];
__device__ float d_biasp[GATES];
__device__ float d_hbuf[2 * BATCH * HID]; // double-buffered h (tf32-rounded)
__device__ unsigned g_bar;

__device__ __forceinline__ float f2tf32(float f) {
    unsigned u;
    asm("cvt.rna.tf32.f32 %0, %1;" : "=r"(u) : "f"(f));
    return __uint_as_float(u);
}

__device__ __forceinline__ void mma_tf32(float* c, const unsigned* a, const unsigned* b) {
    asm volatile(
        "mma.sync.aligned.m16n8k8.row.col.f32.tf32.tf32.f32 "
        "{%0,%1,%2,%3}, {%4,%5,%6,%7}, {%8,%9}, {%0,%1,%2,%3};\n"
        : "+f"(c[0]), "+f"(c[1]), "+f"(c[2]), "+f"(c[3])
        : "r"(a[0]), "r"(a[1]), "r"(a[2]), "r"(a[3]), "r"(b[0]), "r"(b[1]));
}

__device__ __forceinline__ float sigm(float x) { return 1.0f / (1.0f + expf(-x)); }

#define CP_ASYNC_CG(dst, src) \
    asm volatile("cp.async.cg.shared.global [%0], [%1], 16;\n" :: "r"(dst), "l"(src))
#define CP_COMMIT() asm volatile("cp.async.commit_group;\n")
#define CP_WAIT(n)  asm volatile("cp.async.wait_group %0;\n" :: "n"(n))

// ---------------------------------------------------------------------------
__global__ void prep_kernel(const float* __restrict__ x,
                            const float* __restrict__ W, const float* __restrict__ U,
                            const float* __restrict__ bih, const float* __restrict__ bhh) {
    int tid = blockIdx.x * blockDim.x + threadIdx.x;
    int stride = gridDim.x * blockDim.x;
    if (tid == 0) g_bar = 0u;

    for (int idx = tid; idx < GATES * HID; idx += stride) {
        int jp = idx >> 10, k = idx & 1023;
        int blk = jp >> 5, r = jp & 31;
        int gate = r >> 3, u = r & 7;
        int j = gate * HID + (blk * 8 + u);
        d_Wp[idx] = f2tf32(W[j * HID + k]);
        d_Up[idx] = f2tf32(U[j * HID + k]);
    }
    for (int idx = tid; idx < 16777216; idx += stride) d_xr[idx] = f2tf32(x[idx]);
    for (int idx = tid; idx < GATES; idx += stride) {
        int blk = idx >> 5, r = idx & 31;
        int gate = r >> 3, u = r & 7;
        int j = gate * HID + (blk * 8 + u);
        d_biasp[idx] = bih[j] + bhh[j];
    }
    for (int idx = tid; idx < 2 * BATCH * HID; idx += stride) d_hbuf[idx] = 0.0f;
}

// ---------------------------------------------------------------------------
// Phase 1: xg = xr @ Wp^T + bias   (M=16384, N=4096, K=1024)
// ---------------------------------------------------------------------------
#define P1_S 36

__global__ __launch_bounds__(256, 2) void gemm_xg() {
    extern __shared__ float sm1[];
    float* As = sm1;                  // [2][128*36]
    float* Bs = sm1 + 2 * 128 * P1_S; // [2][128*36]

    const int n0 = blockIdx.x * 128;
    const int m0 = blockIdx.y * 128;
    const int tid = threadIdx.x;
    const int warp = tid >> 5, lane = tid & 31;
    const int wm = warp >> 2, wn = warp & 3;
    const int gid = lane >> 2, tg = lane & 3;

    float acc[4][4][4];
#pragma unroll
    for (int i = 0; i < 4; i++)
#pragma unroll
        for (int j = 0; j < 4; j++)
#pragma unroll
            for (int k = 0; k < 4; k++) acc[i][j][k] = 0.0f;

    const float* Ag = d_xr + (size_t)m0 * HID;
    const float* Bg = d_Wp + (size_t)n0 * HID;

    auto load_stage = [&](int kt, int st) {
        float* Ad = As + st * 128 * P1_S;
        float* Bd = Bs + st * 128 * P1_S;
        const int k0 = kt * 32;
#pragma unroll
        for (int l = 0; l < 4; l++) {
            int i = tid + l * 256;           // 0..1023
            int row = i >> 3, v = (i & 7) * 4;
            unsigned da = (unsigned)__cvta_generic_to_shared(Ad + row * P1_S + v);
            CP_ASYNC_CG(da, Ag + (size_t)row * HID + k0 + v);
            unsigned db = (unsigned)__cvta_generic_to_shared(Bd + row * P1_S + v);
            CP_ASYNC_CG(db, Bg + (size_t)row * HID + k0 + v);
        }
        CP_COMMIT();
    };

    load_stage(0, 0);
    for (int kt = 0; kt < 32; kt++) {
        if (kt + 1 < 32) { load_stage(kt + 1, (kt + 1) & 1); CP_WAIT(1); }
        else             { CP_WAIT(0); }
        __syncthreads();
        const float* Ac = As + (kt & 1) * 128 * P1_S;
        const float* Bc = Bs + (kt & 1) * 128 * P1_S;
#pragma unroll
        for (int kk = 0; kk < 4; kk++) {
            const int kc = kk * 8 + tg;
            unsigned a[4][4], b[4][2];
#pragma unroll
            for (int mf = 0; mf < 4; mf++) {
                int row = wm * 64 + mf * 16 + gid;
                a[mf][0] = __float_as_uint(Ac[row * P1_S + kc]);
                a[mf][1] = __float_as_uint(Ac[(row + 8) * P1_S + kc]);
                a[mf][2] = __float_as_uint(Ac[row * P1_S + kc + 4]);
                a[mf][3] = __float_as_uint(Ac[(row + 8) * P1_S + kc + 4]);
            }
#pragma unroll
            for (int nf = 0; nf < 4; nf++) {
                int col = wn * 32 + nf * 8 + gid;
                b[nf][0] = __float_as_uint(Bc[col * P1_S + kc]);
                b[nf][1] = __float_as_uint(Bc[col * P1_S + kc + 4]);
            }
#pragma unroll
            for (int mf = 0; mf < 4; mf++)
#pragma unroll
                for (int nf = 0; nf < 4; nf++) mma_tf32(acc[mf][nf], a[mf], b[nf]);
        }
        __syncthreads();
    }

#pragma unroll
    for (int mf = 0; mf < 4; mf++)
#pragma unroll
        for (int nf = 0; nf < 4; nf++) {
            int row = m0 + wm * 64 + mf * 16 + gid;
            int col = n0 + wn * 32 + nf * 8 + 2 * tg;
            float b0 = d_biasp[col], b1 = d_biasp[col + 1];
            d_xg[(size_t)row * GATES + col]           = acc[mf][nf][0] + b0;
            d_xg[(size_t)row * GATES + col + 1]       = acc[mf][nf][1] + b1;
            d_xg[(size_t)(row + 8) * GATES + col]     = acc[mf][nf][2] + b0;
            d_xg[(size_t)(row + 8) * GATES + col + 1] = acc[mf][nf][3] + b1;
        }
}

// ---------------------------------------------------------------------------
// Phase 2: persistent recurrence. 128 CTAs, CTA owns 32 gate-rows, full K.
// smem (floats): Us 32x1028 | hs 2x32x260 | rb 4x(32x33) | xs 32x36
// ---------------------------------------------------------------------------
#define SU 1028
#define SH 260
#define RBS (32 * 33)
#define OFF_HS (32 * SU)                  // 32896
#define OFF_RB (OFF_HS + 2 * 32 * SH)     // 49536
#define OFF_XS (OFF_RB + 4 * RBS)         // 53760
#define SM2_FLOATS (OFF_XS + 32 * 36)     // 54912 -> 219,648 B

__global__ __launch_bounds__(256, 1) void lstm_kernel(float* __restrict__ out) {
    extern __shared__ float sm[];
    float* Us = sm;
    float* hs = sm + OFF_HS;
    float* rb = sm + OFF_RB;
    float* xs = sm + OFF_XS;

    const int cta = blockIdx.x;
    const int tid = threadIdx.x;
    const int warp = tid >> 5, lane = tid & 31;
    const int gid = lane >> 2, tg = lane & 3;

    const unsigned long long barp =
        (unsigned long long)__cvta_generic_to_global(&g_bar);

    // stage U'' slice (rows 32*cta .. +31, all K) once
    const float* Ug = d_Up + (size_t)(32 * cta) * HID;
    for (int i = tid; i < 32 * 256; i += 256) {
        int row = i >> 8, v = (i & 255) * 4;
        *(float4*)(Us + row * SU + v) = *(const float4*)(Ug + row * HID + v);
    }
    __syncthreads();

    const int tu = tid >> 5, tb = tid & 31;   // gate-math thread owns (u=tu,b=tb)
    float c_reg = 0.0f;

    for (int t = 0; t < T_STEPS; t++) {
        const float* hb = d_hbuf + (t & 1) * (BATCH * HID);

        // prefetch xg tile [32 b][32 j] for this step (group 0)
        {
            int row = tid >> 3, q = tid & 7;   // 32 rows x 8 float4
            unsigned d = (unsigned)__cvta_generic_to_shared(xs + row * 36 + q * 4);
            CP_ASYNC_CG(d, d_xg + (size_t)(t * BATCH + row) * GATES + 32 * cta + q * 4);
            CP_COMMIT();
        }

        auto load_chunk = [&](int ch, int bi) {
#pragma unroll
            for (int l = 0; l < 8; l++) {
                int i = tid + l * 256;
                int row = i >> 6, v = (i & 63) * 4;
                unsigned d = (unsigned)__cvta_generic_to_shared(
                    hs + bi * (32 * SH) + row * SH + v);
                CP_ASYNC_CG(d, hb + row * HID + ch * 256 + v);
            }
            CP_COMMIT();
        };

        float acc[2][4][4];
#pragma unroll
        for (int i = 0; i < 2; i++)
#pragma unroll
            for (int j = 0; j < 4; j++)
#pragma unroll
                for (int k = 0; k < 4; k++) acc[i][j][k] = 0.0f;

        auto mma_chunk = [&](int ch, int bi) {
            const float* hc = hs + bi * (32 * SH);
            const int kb = warp * 32;
#pragma unroll
            for (int kk = 0; kk < 4; kk++) {
                const int kcl = kb + kk * 8 + tg;
                const int kcu = ch * 256 + kcl;
                unsigned a[2][4];
#pragma unroll
                for (int mt = 0; mt < 2; mt++) {
                    int row = mt * 16 + gid;
                    a[mt][0] = __float_as_uint(Us[row * SU + kcu]);
                    a[mt][1] = __float_as_uint(Us[(row + 8) * SU + kcu]);
                    a[mt][2] = __float_as_uint(Us[row * SU + kcu + 4]);
                    a[mt][3] = __float_as_uint(Us[(row + 8) * SU + kcu + 4]);
                }
#pragma unroll
                for (int nf = 0; nf < 4; nf++) {
                    unsigned b[2];
                    b[0] = __float_as_uint(hc[(nf * 8 + gid) * SH + kcl]);
                    b[1] = __float_as_uint(hc[(nf * 8 + gid) * SH + kcl + 4]);
#pragma unroll
                    for (int mt = 0; mt < 2; mt++) mma_tf32(acc[mt][nf], a[mt], b);
                }
            }
        };

        load_chunk(0, 0);                         // pending: xs,c0
        load_chunk(1, 1);                         // pending: xs,c0,c1
        CP_WAIT(1); __syncthreads();              // xs,c0 done
        mma_chunk(0, 0);
        __syncthreads();                          // buf0 free
        load_chunk(2, 0);                         // pending: c1,c2
        CP_WAIT(1); __syncthreads();              // c1 done
        mma_chunk(1, 1);
        __syncthreads();                          // buf1 free
        load_chunk(3, 1);                         // pending: c2,c3
        CP_WAIT(1); __syncthreads();              // c2 done
        mma_chunk(2, 0);
        CP_WAIT(0); __syncthreads();              // c3 done
        mma_chunk(3, 1);

        // two-phase reduce: warps 0-3 dump, warps 4-7 accumulate into them
        {
            float* rbw = rb + (warp & 3) * RBS;
            if (warp < 4) {
#pragma unroll
                for (int mt = 0; mt < 2; mt++)
#pragma unroll
                    for (int nf = 0; nf < 4; nf++) {
                        int row = mt * 16 + gid;
                        int col = nf * 8 + 2 * tg;
                        rbw[row * 33 + col]           = acc[mt][nf][0];
                        rbw[row * 33 + col + 1]       = acc[mt][nf][1];
                        rbw[(row + 8) * 33 + col]     = acc[mt][nf][2];
                        rbw[(row + 8) * 33 + col + 1] = acc[mt][nf][3];
                    }
            }
            __syncthreads();
            if (warp >= 4) {
#pragma unroll
                for (int mt = 0; mt < 2; mt++)
#pragma unroll
                    for (int nf = 0; nf < 4; nf++) {
                        int row = mt * 16 + gid;
                        int col = nf * 8 + 2 * tg;
                        rbw[row * 33 + col]           += acc[mt][nf][0];
                        rbw[row * 33 + col + 1]       += acc[mt][nf][1];
                        rbw[(row + 8) * 33 + col]     += acc[mt][nf][2];
                        rbw[(row + 8) * 33 + col + 1] += acc[mt][nf][3];
                    }
            }
            __syncthreads();
        }

        // gate math
        {
            float v[4];
#pragma unroll
            for (int gate = 0; gate < 4; gate++) {
                int r = gate * 8 + tu;
                float s = xs[tb * 36 + r];
#pragma unroll
                for (int p = 0; p < 4; p++) s += rb[p * RBS + r * 33 + tb];
                v[gate] = s;
            }
            float it = sigm(v[0]);
            float ft = sigm(v[1]);
            float ch = tanhf(v[2]);
            float ot = sigm(v[3]);
            c_reg = ft * c_reg + it * ch;
            float h = ot * tanhf(c_reg);
            int n = 8 * cta + tu;
            out[(size_t)t * (BATCH * HID) + tb * HID + n] = h;
            d_hbuf[((t + 1) & 1) * (BATCH * HID) + tb * HID + n] = f2tf32(h);
            if (t == T_STEPS - 1) {
                out[16777216 + tb * HID + n] = h;
                out[16777216 + 32768 + tb * HID + n] = c_reg;
            }
        }

        // global barrier: release arrive + acquire spin (no membar.gpu)
        __syncthreads();
        if (tid == 0) {
            asm volatile("red.release.gpu.global.add.u32 [%0], %1;"
                         :: "l"(barp), "r"(1u) : "memory");
            const unsigned target = 128u * (unsigned)(t + 1);
            unsigned v;
            do {
                asm volatile("ld.acquire.gpu.global.u32 %0, [%1];"
                             : "=r"(v) : "l"(barp) : "memory");
            } while (v < target);
        }
        __syncthreads();
    }
}

// ---------------------------------------------------------------------------
extern "C" void kernel_launch(void* const* d_in, const int* in_sizes, int n_in,
                              void* d_out, int out_size) {
    (void)in_sizes; (void)n_in; (void)out_size;
    const float* x   = (const float*)d_in[0];
    const float* W   = (const float*)d_in[1];
    const float* U   = (const float*)d_in[2];
    const float* bih = (const float*)d_in[3];
    const float* bhh = (const float*)d_in[4];
    float* out = (float*)d_out;

    static int inited = 0;
    const int smem1 = 2 * 2 * 128 * P1_S * 4;     // 73,728
    const int smem2 = SM2_FLOATS * 4;             // 219,648
    if (!inited) {
        cudaFuncSetAttribute(gemm_xg, cudaFuncAttributeMaxDynamicSharedMemorySize, smem1);
        cudaFuncSetAttribute(lstm_kernel, cudaFuncAttributeMaxDynamicSharedMemorySize, smem2);
        inited = 1;
    }

    prep_kernel<<<4096, 256>>>(x, W, U, bih, bhh);
    dim3 g1(32, 128);
    gemm_xg<<<g1, 256, smem1>>>();
    lstm_kernel<<<128, 256, smem2>>>(out);
}

// round 4
// speedup vs baseline: 4.1369x; 1.0641x over previous
#include <cuda_runtime.h>

// ---------------------------------------------------------------------------
// LSTM_6786048328562 : T=512, B=32, I=H=1024  (fp32 in/out, tf32 tensor math)
//   out = [ output(512*32*1024) | h_n(32*1024) | c_n(32*1024) ]
//
// Row reorder:  j'' = 32*blk + gate*8 + u   (hidden n = 8*blk + u, blk=0..127)
//
// prep    : reorder+tf32-round W,U; tf32-round x; bias; zero h; bar=0
// gemm_xg : xg = xr @ W''^T + bias  (tf32 mma, 128x128x32, 2-stage cp.async)
// lstm    : persistent 128 CTAs. U'' fragments hoisted into REGISTERS
//           (one-time SMEM staging, then SMEM reused as 4 h-chunk buffers).
//           Per step: issue xg(t+1) + all 4 h chunks at once (cp.async),
//           progressive wait/mma, two-phase smem reduce, gate math (c in
//           regs), coalesced h/out stores via smem transpose, ONE
//           release/acquire global barrier; out stores overlap the spin.
// ---------------------------------------------------------------------------

#define T_STEPS 512
#define BATCH   32
#define HID     1024
#define GATES   4096

__device__ float d_xg[67108864];          // [16384][4096]
__device__ float d_xr[16777216];          // tf32-rounded x
__device__ float d_Wp[GATES * HID];
__device__ float d_Up[GATES * HID];
__device__ float d_biasp[GATES];
__device__ float d_hbuf[2 * BATCH * HID]; // double-buffered h (tf32-rounded)
__device__ unsigned g_bar;

__device__ __forceinline__ float f2tf32(float f) {
    unsigned u;
    asm("cvt.rna.tf32.f32 %0, %1;" : "=r"(u) : "f"(f));
    return __uint_as_float(u);
}

__device__ __forceinline__ void mma_tf32(float* c, const unsigned* a, const unsigned* b) {
    asm volatile(
        "mma.sync.aligned.m16n8k8.row.col.f32.tf32.tf32.f32 "
        "{%0,%1,%2,%3}, {%4,%5,%6,%7}, {%8,%9}, {%0,%1,%2,%3};\n"
        : "+f"(c[0]), "+f"(c[1]), "+f"(c[2]), "+f"(c[3])
        : "r"(a[0]), "r"(a[1]), "r"(a[2]), "r"(a[3]), "r"(b[0]), "r"(b[1]));
}

__device__ __forceinline__ float sigm(float x) { return 1.0f / (1.0f + expf(-x)); }

#define CP_ASYNC_CG(dst, src) \
    asm volatile("cp.async.cg.shared.global [%0], [%1], 16;\n" :: "r"(dst), "l"(src))
#define CP_COMMIT() asm volatile("cp.async.commit_group;\n")
#define CP_WAIT(n)  asm volatile("cp.async.wait_group %0;\n" :: "n"(n))

// ---------------------------------------------------------------------------
__global__ void prep_kernel(const float* __restrict__ x,
                            const float* __restrict__ W, const float* __restrict__ U,
                            const float* __restrict__ bih, const float* __restrict__ bhh) {
    int tid = blockIdx.x * blockDim.x + threadIdx.x;
    int stride = gridDim.x * blockDim.x;
    if (tid == 0) g_bar = 0u;

    for (int idx = tid; idx < GATES * HID; idx += stride) {
        int jp = idx >> 10, k = idx & 1023;
        int blk = jp >> 5, r = jp & 31;
        int gate = r >> 3, u = r & 7;
        int j = gate * HID + (blk * 8 + u);
        d_Wp[idx] = f2tf32(W[j * HID + k]);
        d_Up[idx] = f2tf32(U[j * HID + k]);
    }
    for (int idx = tid; idx < 16777216; idx += stride) d_xr[idx] = f2tf32(x[idx]);
    for (int idx = tid; idx < GATES; idx += stride) {
        int blk = idx >> 5, r = idx & 31;
        int gate = r >> 3, u = r & 7;
        int j = gate * HID + (blk * 8 + u);
        d_biasp[idx] = bih[j] + bhh[j];
    }
    for (int idx = tid; idx < 2 * BATCH * HID; idx += stride) d_hbuf[idx] = 0.0f;
}

// ---------------------------------------------------------------------------
// Phase 1: xg = xr @ Wp^T + bias   (M=16384, N=4096, K=1024)
// ---------------------------------------------------------------------------
#define P1_S 36

__global__ __launch_bounds__(256, 2) void gemm_xg() {
    extern __shared__ float sm1[];
    float* As = sm1;
    float* Bs = sm1 + 2 * 128 * P1_S;

    const int n0 = blockIdx.x * 128;
    const int m0 = blockIdx.y * 128;
    const int tid = threadIdx.x;
    const int warp = tid >> 5, lane = tid & 31;
    const int wm = warp >> 2, wn = warp & 3;
    const int gid = lane >> 2, tg = lane & 3;

    float acc[4][4][4];
#pragma unroll
    for (int i = 0; i < 4; i++)
#pragma unroll
        for (int j = 0; j < 4; j++)
#pragma unroll
            for (int k = 0; k < 4; k++) acc[i][j][k] = 0.0f;

    const float* Ag = d_xr + (size_t)m0 * HID;
    const float* Bg = d_Wp + (size_t)n0 * HID;

    auto load_stage = [&](int kt, int st) {
        float* Ad = As + st * 128 * P1_S;
        float* Bd = Bs + st * 128 * P1_S;
        const int k0 = kt * 32;
#pragma unroll
        for (int l = 0; l < 4; l++) {
            int i = tid + l * 256;
            int row = i >> 3, v = (i & 7) * 4;
            unsigned da = (unsigned)__cvta_generic_to_shared(Ad + row * P1_S + v);
            CP_ASYNC_CG(da, Ag + (size_t)row * HID + k0 + v);
            unsigned db = (unsigned)__cvta_generic_to_shared(Bd + row * P1_S + v);
            CP_ASYNC_CG(db, Bg + (size_t)row * HID + k0 + v);
        }
        CP_COMMIT();
    };

    load_stage(0, 0);
    for (int kt = 0; kt < 32; kt++) {
        if (kt + 1 < 32) { load_stage(kt + 1, (kt + 1) & 1); CP_WAIT(1); }
        else             { CP_WAIT(0); }
        __syncthreads();
        const float* Ac = As + (kt & 1) * 128 * P1_S;
        const float* Bc = Bs + (kt & 1) * 128 * P1_S;
#pragma unroll
        for (int kk = 0; kk < 4; kk++) {
            const int kc = kk * 8 + tg;
            unsigned a[4][4], b[4][2];
#pragma unroll
            for (int mf = 0; mf < 4; mf++) {
                int row = wm * 64 + mf * 16 + gid;
                a[mf][0] = __float_as_uint(Ac[row * P1_S + kc]);
                a[mf][1] = __float_as_uint(Ac[(row + 8) * P1_S + kc]);
                a[mf][2] = __float_as_uint(Ac[row * P1_S + kc + 4]);
                a[mf][3] = __float_as_uint(Ac[(row + 8) * P1_S + kc + 4]);
            }
#pragma unroll
            for (int nf = 0; nf < 4; nf++) {
                int col = wn * 32 + nf * 8 + gid;
                b[nf][0] = __float_as_uint(Bc[col * P1_S + kc]);
                b[nf][1] = __float_as_uint(Bc[col * P1_S + kc + 4]);
            }
#pragma unroll
            for (int mf = 0; mf < 4; mf++)
#pragma unroll
                for (int nf = 0; nf < 4; nf++) mma_tf32(acc[mf][nf], a[mf], b[nf]);
        }
        __syncthreads();
    }

#pragma unroll
    for (int mf = 0; mf < 4; mf++)
#pragma unroll
        for (int nf = 0; nf < 4; nf++) {
            int row = m0 + wm * 64 + mf * 16 + gid;
            int col = n0 + wn * 32 + nf * 8 + 2 * tg;
            float b0 = d_biasp[col], b1 = d_biasp[col + 1];
            d_xg[(size_t)row * GATES + col]           = acc[mf][nf][0] + b0;
            d_xg[(size_t)row * GATES + col + 1]       = acc[mf][nf][1] + b1;
            d_xg[(size_t)(row + 8) * GATES + col]     = acc[mf][nf][2] + b0;
            d_xg[(size_t)(row + 8) * GATES + col + 1] = acc[mf][nf][3] + b1;
        }
}

// ---------------------------------------------------------------------------
// Phase 2: persistent recurrence. 128 CTAs, CTA owns 32 gate-rows, full K.
// smem (floats): hs 4x32x260 | rb 4x(32x33) | xs 2x32x36 | hstg 32x9
// ---------------------------------------------------------------------------
#define SH 260
#define RBS (32 * 33)
#define OFF_RB (4 * 32 * SH)              // 33280
#define OFF_XS (OFF_RB + 4 * RBS)         // 37504
#define OFF_HSTG (OFF_XS + 2 * 32 * 36)   // 39808
#define SM2_FLOATS (OFF_HSTG + 32 * 9)    // 40096 -> 160,384 B

__global__ __launch_bounds__(256, 1) void lstm_kernel(float* __restrict__ out) {
    extern __shared__ float sm[];
    float* hs   = sm;              // 4 chunk buffers [ch][32][SH]
    float* rb   = sm + OFF_RB;
    float* xs   = sm + OFF_XS;
    float* hstg = sm + OFF_HSTG;

    const int cta = blockIdx.x;
    const int tid = threadIdx.x;
    const int warp = tid >> 5, lane = tid & 31;
    const int gid = lane >> 2, tg = lane & 3;

    const unsigned long long barp =
        (unsigned long long)__cvta_generic_to_global(&g_bar);

    // ---- stage U'' fragments into registers (one-time) ----
    // aF[ch][kk][mt][4]: A-fragment for chunk ch (k in [256ch,256ch+256)),
    // sub-k kk, row-half mt. 128 regs.
    unsigned aF[4][4][2][4];
    {
        const float* Ug = d_Up + (size_t)(32 * cta) * HID;
        for (int ch = 0; ch < 4; ch++) {
            for (int i = tid; i < 32 * 64; i += 256) {
                int row = i >> 6, v = (i & 63) * 4;
                *(float4*)(hs + row * SH + v) =
                    *(const float4*)(Ug + row * HID + ch * 256 + v);
            }
            __syncthreads();
#pragma unroll
            for (int kk = 0; kk < 4; kk++) {
                const int kc = warp * 32 + kk * 8 + tg;
#pragma unroll
                for (int mt = 0; mt < 2; mt++) {
                    int row = mt * 16 + gid;
                    aF[ch][kk][mt][0] = __float_as_uint(hs[row * SH + kc]);
                    aF[ch][kk][mt][1] = __float_as_uint(hs[(row + 8) * SH + kc]);
                    aF[ch][kk][mt][2] = __float_as_uint(hs[row * SH + kc + 4]);
                    aF[ch][kk][mt][3] = __float_as_uint(hs[(row + 8) * SH + kc + 4]);
                }
            }
            __syncthreads();
        }
    }

    // prefetch xg for t=0 into xs[0]
    {
        int row = tid >> 3, q = tid & 7;
        unsigned d = (unsigned)__cvta_generic_to_shared(xs + row * 36 + q * 4);
        CP_ASYNC_CG(d, d_xg + (size_t)row * GATES + 32 * cta + q * 4);
        CP_COMMIT();
    }

    const int tu = tid >> 5, tb = tid & 31;
    float c_reg = 0.0f;

    // epilogue write mapping: warp w handles b = 4w..4w+3, lane -> (b,u)
    const int wb = 4 * warp + (lane >> 3);
    const int wu = lane & 7;
    const int wn_idx = 8 * cta + wu;          // hidden-gmem column

    for (int t = 0; t < T_STEPS; t++) {
        const float* hb = d_hbuf + (t & 1) * (BATCH * HID);

        // issue xg(t+1) prefetch (off critical path) + all 4 h chunks
        if (t + 1 < T_STEPS) {
            int row = tid >> 3, q = tid & 7;
            unsigned d = (unsigned)__cvta_generic_to_shared(
                xs + ((t + 1) & 1) * (32 * 36) + row * 36 + q * 4);
            CP_ASYNC_CG(d, d_xg + (size_t)((t + 1) * BATCH + row) * GATES
                            + 32 * cta + q * 4);
            CP_COMMIT();
        }
#pragma unroll
        for (int ch = 0; ch < 4; ch++) {
#pragma unroll
            for (int l = 0; l < 8; l++) {
                int i = tid + l * 256;
                int row = i >> 6, v = (i & 63) * 4;
                unsigned d = (unsigned)__cvta_generic_to_shared(
                    hs + ch * (32 * SH) + row * SH + v);
                CP_ASYNC_CG(d, hb + row * HID + ch * 256 + v);
            }
            CP_COMMIT();
        }

        float acc[2][4][4];
#pragma unroll
        for (int i = 0; i < 2; i++)
#pragma unroll
            for (int j = 0; j < 4; j++)
#pragma unroll
                for (int k = 0; k < 4; k++) acc[i][j][k] = 0.0f;

        auto mma_chunk = [&](int ch) {
            const float* hc = hs + ch * (32 * SH);
            const int kb = warp * 32;
#pragma unroll
            for (int kk = 0; kk < 4; kk++) {
                const int kcl = kb + kk * 8 + tg;
#pragma unroll
                for (int nf = 0; nf < 4; nf++) {
                    unsigned b[2];
                    b[0] = __float_as_uint(hc[(nf * 8 + gid) * SH + kcl]);
                    b[1] = __float_as_uint(hc[(nf * 8 + gid) * SH + kcl + 4]);
#pragma unroll
                    for (int mt = 0; mt < 2; mt++)
                        mma_tf32(acc[mt][nf], aF[ch][kk][mt], b);
                }
            }
        };

        CP_WAIT(3); __syncthreads(); mma_chunk(0);
        CP_WAIT(2); __syncthreads(); mma_chunk(1);
        CP_WAIT(1); __syncthreads(); mma_chunk(2);
        CP_WAIT(0); __syncthreads(); mma_chunk(3);

        // two-phase reduce: warps 0-3 dump, warps 4-7 accumulate
        {
            float* rbw = rb + (warp & 3) * RBS;
            if (warp < 4) {
#pragma unroll
                for (int mt = 0; mt < 2; mt++)
#pragma unroll
                    for (int nf = 0; nf < 4; nf++) {
                        int row = mt * 16 + gid;
                        int col = nf * 8 + 2 * tg;
                        rbw[row * 33 + col]           = acc[mt][nf][0];
                        rbw[row * 33 + col + 1]       = acc[mt][nf][1];
                        rbw[(row + 8) * 33 + col]     = acc[mt][nf][2];
                        rbw[(row + 8) * 33 + col + 1] = acc[mt][nf][3];
                    }
            }
            __syncthreads();
            if (warp >= 4) {
#pragma unroll
                for (int mt = 0; mt < 2; mt++)
#pragma unroll
                    for (int nf = 0; nf < 4; nf++) {
                        int row = mt * 16 + gid;
                        int col = nf * 8 + 2 * tg;
                        rbw[row * 33 + col]           += acc[mt][nf][0];
                        rbw[row * 33 + col + 1]       += acc[mt][nf][1];
                        rbw[(row + 8) * 33 + col]     += acc[mt][nf][2];
                        rbw[(row + 8) * 33 + col + 1] += acc[mt][nf][3];
                    }
            }
            __syncthreads();
        }

        // gate math (thread owns u=tu, b=tb); stage h into transpose buffer
        float c_save = 0.0f;
        {
            const float* xgr = xs + (t & 1) * (32 * 36) + tb * 36;
            float v[4];
#pragma unroll
            for (int gate = 0; gate < 4; gate++) {
                int r = gate * 8 + tu;
                float s = xgr[r];
#pragma unroll
                for (int p = 0; p < 4; p++) s += rb[p * RBS + r * 33 + tb];
                v[gate] = s;
            }
            float it = sigm(v[0]);
            float ft = sigm(v[1]);
            float ch = tanhf(v[2]);
            float ot = sigm(v[3]);
            c_reg = ft * c_reg + it * ch;
            c_save = c_reg;
            float h = ot * tanhf(c_reg);
            hstg[tb * 9 + tu] = h;
        }
        __syncthreads();

        // coalesced h write to d_hbuf (tf32-rounded) — before release
        float hval = hstg[wb * 9 + wu];
        if (t + 1 < T_STEPS)
            d_hbuf[((t + 1) & 1) * (BATCH * HID) + wb * HID + wn_idx] = f2tf32(hval);

        // barrier arrive (release), then out writes overlap the spin
        if (tid == 0)
            asm volatile("red.release.gpu.global.add.u32 [%0], %1;"
                         :: "l"(barp), "r"(1u) : "memory");

        out[(size_t)t * (BATCH * HID) + wb * HID + wn_idx] = hval;
        if (t == T_STEPS - 1) {
            out[16777216 + wb * HID + wn_idx] = hval;         // h_n
            // stage c and write coalesced
            __syncthreads();
            hstg[tb * 9 + tu] = c_save;
            __syncthreads();
            out[16777216 + 32768 + wb * HID + wn_idx] = hstg[wb * 9 + wu];
        }

        if (tid == 0) {
            const unsigned target = 128u * (unsigned)(t + 1);
            unsigned v;
            do {
                asm volatile("ld.acquire.gpu.global.u32 %0, [%1];"
                             : "=r"(v) : "l"(barp) : "memory");
            } while (v < target);
        }
        __syncthreads();
    }
}

// ---------------------------------------------------------------------------
extern "C" void kernel_launch(void* const* d_in, const int* in_sizes, int n_in,
                              void* d_out, int out_size) {
    (void)in_sizes; (void)n_in; (void)out_size;
    const float* x   = (const float*)d_in[0];
    const float* W   = (const float*)d_in[1];
    const float* U   = (const float*)d_in[2];
    const float* bih = (const float*)d_in[3];
    const float* bhh = (const float*)d_in[4];
    float* out = (float*)d_out;

    static int inited = 0;
    const int smem1 = 2 * 2 * 128 * P1_S * 4;     // 73,728
    const int smem2 = SM2_FLOATS * 4;             // 160,384
    if (!inited) {
        cudaFuncSetAttribute(gemm_xg, cudaFuncAttributeMaxDynamicSharedMemorySize, smem1);
        cudaFuncSetAttribute(lstm_kernel, cudaFuncAttributeMaxDynamicSharedMemorySize, smem2);
        inited = 1;
    }

    prep_kernel<<<4096, 256>>>(x, W, U, bih, bhh);
    dim3 g1(32, 128);
    gemm_xg<<<g1, 256, smem1>>>();
    lstm_kernel<<<128, 256, smem2>>>(out);
}